// round 7
// baseline (speedup 1.0000x reference)
#include <cuda_runtime.h>

// NoQmix_74560632258885 — FINAL (R6 resubmit; R6 bench was an infra failure:
// "GB300 container failed twice", no measurement taken)
//
// Algebraic identity (verified R1-R5, rel_err ~1.7e-7): softmax(e, axis=1) is
// normalized over the same axis the final einsum ('bij,bj->b') sums over, so
// Σ_i attention[b,i,j] == 1 for every (b, j) — including fully-masked columns
// (uniform softmax still sums to 1). Hence
//   q_tot[b] = Σ_j agent_qs[b,j]
// independent of features, adj, states, W, a. The 34-GFLOP GAT pipeline in
// the reference is algebraically dead.
//
// Measured design space (total us / ncu kernel us):
//   512blk*256/MLP1: 6.18/4.35   64blk*256/MLP4: 6.11/4.38
//   128blk*256/MLP2: 6.18/4.32   32blk*256/MLP8: 6.82/5.25 (SM starvation)
//   128blk*128/MLP4: 6.08/4.67   <- best so far
// => >=64-block plateau at ~6.1 (timer tick = 0.064us); duration = fixed
// replay/launch overhead + one memory-latency exposure. R6 closes the last
// gap: 128 CTAs left 20 of 148 SMs idle; 256 CTAs x 64 threads puts at least
// one CTA on every SM with the same per-thread work and coalescing (one warp
// = 8 consecutive rows = 2KB contiguous).

__global__ void __launch_bounds__(64)
rowsum64_final_kernel(const float4* __restrict__ qs4,
                      float* __restrict__ out,
                      int rows) {
    int t = blockIdx.x * blockDim.x + threadIdx.x;   // global thread id
    int row = t >> 2;                                 // 4 threads per row
    if (row >= rows) return;

    // Thread t owns float4 indices [4t, 4t+3] — 64B contiguous, 4 independent
    // LDG.128 in flight per thread.
    const float4* p = qs4 + 4 * t;
    float4 v0 = p[0];
    float4 v1 = p[1];
    float4 v2 = p[2];
    float4 v3 = p[3];

    float s = ((v0.x + v0.y) + (v0.z + v0.w))
            + ((v1.x + v1.y) + (v1.z + v1.w))
            + ((v2.x + v2.y) + (v2.z + v2.w))
            + ((v3.x + v3.y) + (v3.z + v3.w));

    // Reduce across the 4 lanes of this row (consecutive in-warp).
    s += __shfl_xor_sync(0xffffffffu, s, 2);
    s += __shfl_xor_sync(0xffffffffu, s, 1);

    if ((t & 3) == 0) out[row] = s;
}

extern "C" void kernel_launch(void* const* d_in, const int* in_sizes, int n_in,
                              void* d_out, int out_size) {
    // metadata order: features[0], agent_qs[1], adj[2], states[3], W[4], a[5]
    const float4* agent_qs4 = (const float4*)d_in[1];
    float* out = (float*)d_out;

    int rows = out_size;                 // B = 4096
    int total_threads = rows * 4;        // 4 threads per row
    int threads = 64;                    // 256 CTAs -> every SM covered
    int blocks = (total_threads + threads - 1) / threads;   // 256

    rowsum64_final_kernel<<<blocks, threads>>>(agent_qs4, out, rows);
}

// round 8
// speedup vs baseline: 1.1925x; 1.1925x over previous
#include <cuda_runtime.h>

// NoQmix_74560632258885 — FINAL (revert to R5, the measured optimum)
//
// Algebraic identity (verified R1-R7, rel_err ~1.7e-7): softmax(e, axis=1) is
// normalized over the same axis the final einsum ('bij,bj->b') sums over, so
// Σ_i attention[b,i,j] == 1 for every (b, j) — including fully-masked columns
// (uniform softmax still sums to 1). Hence
//   q_tot[b] = Σ_j agent_qs[b,j]
// independent of features, adj, states, W, a. The 34-GFLOP GAT pipeline in
// the reference is algebraically dead; the kernel is a 4096x64 fp32 row-sum.
//
// Complete measured design space (total us):
//   128blk*128/MLP4: 6.08  <- THIS (best)
//   64blk*256/MLP4:  6.11
//   256blk*64/MLP4:  6.14
//   512blk*256/MLP1: 6.18   128blk*256/MLP2: 6.18
//   32blk*256/MLP8:  6.82  (SM starvation)
// All >=64-block configs sit within +-1.5 timer ticks (0.064us) of 6.1us:
// duration = fixed graph-replay/launch overhead + one DRAM-latency exposure;
// kernel-internal structure is below measurement resolution. Session win was
// the algebra, not the SASS.

__global__ void __launch_bounds__(128)
rowsum64_final_kernel(const float4* __restrict__ qs4,
                      float* __restrict__ out,
                      int rows) {
    int t = blockIdx.x * blockDim.x + threadIdx.x;   // global thread id
    int row = t >> 2;                                 // 4 threads per row
    if (row >= rows) return;

    // Thread t owns float4 indices [4t, 4t+3] — 64B contiguous, 4 independent
    // LDG.128 in flight per thread.
    const float4* p = qs4 + 4 * t;
    float4 v0 = p[0];
    float4 v1 = p[1];
    float4 v2 = p[2];
    float4 v3 = p[3];

    float s = ((v0.x + v0.y) + (v0.z + v0.w))
            + ((v1.x + v1.y) + (v1.z + v1.w))
            + ((v2.x + v2.y) + (v2.z + v2.w))
            + ((v3.x + v3.y) + (v3.z + v3.w));

    // Reduce across the 4 lanes of this row (consecutive in-warp).
    s += __shfl_xor_sync(0xffffffffu, s, 2);
    s += __shfl_xor_sync(0xffffffffu, s, 1);

    if ((t & 3) == 0) out[row] = s;
}

extern "C" void kernel_launch(void* const* d_in, const int* in_sizes, int n_in,
                              void* d_out, int out_size) {
    // metadata order: features[0], agent_qs[1], adj[2], states[3], W[4], a[5]
    const float4* agent_qs4 = (const float4*)d_in[1];
    float* out = (float*)d_out;

    int rows = out_size;                 // B = 4096
    int total_threads = rows * 4;        // 4 threads per row
    int threads = 128;
    int blocks = (total_threads + threads - 1) / threads;   // 128

    rowsum64_final_kernel<<<blocks, threads>>>(agent_qs4, out, rows);
}